// round 4
// baseline (speedup 1.0000x reference)
#include <cuda_runtime.h>
#include <cstdint>
#include <math.h>

#define ALPHA_CELU 0.1f

// ---------------- device scratch ----------------
__device__ float g_Wp0[4 * 24 * 256 * 16];   // [s][chunk][n][16 perm k]
__device__ float g_Wp1[4 * 16 * 192 * 16];
__device__ float g_Wp2[4 * 12 * 160 * 16];
__device__ float g_partial[256 * 1024];      // [atom][b]
__device__ float g_red[8 * 1024];

// ---------------- helpers ----------------
__device__ __forceinline__ float celu_f(float x) {
    return x > 0.f ? x : ALPHA_CELU * expm1f(x * (1.f / ALPHA_CELU));
}
__device__ __forceinline__ uint32_t tf32r(float x) {   // RNA round to tf32
    uint32_t u;
    asm("cvt.rna.tf32.f32 %0, %1;" : "=r"(u) : "f"(x));
    return u;
}
__device__ __forceinline__ uint32_t smem_u32(const void* p) {
    uint32_t a;
    asm("{ .reg .u64 t; cvta.to.shared.u64 t, %1; cvt.u32.u64 %0, t; }" : "=r"(a) : "l"(p));
    return a;
}
__device__ __forceinline__ void mma_tf32(float c[4],
                                         uint32_t a0, uint32_t a1, uint32_t a2, uint32_t a3,
                                         uint32_t b0, uint32_t b1) {
    asm volatile("mma.sync.aligned.m16n8k8.row.col.f32.tf32.tf32.f32 "
                 "{%0,%1,%2,%3}, {%4,%5,%6,%7}, {%8,%9}, {%0,%1,%2,%3};"
                 : "+f"(c[0]), "+f"(c[1]), "+f"(c[2]), "+f"(c[3])
                 : "r"(a0), "r"(a1), "r"(a2), "r"(a3), "r"(b0), "r"(b1));
}
#define CP_ASYNC16(dst, src) \
    asm volatile("cp.async.ca.shared.global [%0], [%1], 16;" :: "r"(dst), "l"(src))
#define CP_COMMIT() asm volatile("cp.async.commit_group;" ::: "memory")
#define CP_WAIT1()  asm volatile("cp.async.wait_group 1;" ::: "memory")

// ---------------- smem layout (floats) ----------------
// Ys: 128 x 272 (272%32==16 -> conflict-free v4 row pairs)
// Wc: 3 slots x 4096 floats (16KB), rows of 16 floats per n (stride 16)
// Xc: 3 slots x 2560 floats (128 rows x stride 20, plain k order)
#define LDY 272
#define OFF_W (128 * LDY)               // 34816
#define OFF_X (OFF_W + 3 * 4096)        // 47104
#define SMEM_FLOATS (OFF_X + 3 * 2560)  // 54784
#define SMEM_BYTES (SMEM_FLOATS * 4)    // 219136

// ---------------- weight prep: [S,K,N] -> [s][k/16][n][perm(k&15)] tf32 ----------------
template<int K, int N, int WHICH>
__global__ void prep_w(const float* __restrict__ W) {
    int i = blockIdx.x * blockDim.x + threadIdx.x;
    if (i >= 4 * K * N) return;
    float* dst = (WHICH == 0) ? g_Wp0 : (WHICH == 1) ? g_Wp1 : g_Wp2;
    int n = i % N, k = (i / N) % K, s = i / (N * K);
    int chunk = k >> 4, w = k & 15;
    int p = ((w & 3) << 2) | (w >> 2);
    dst[((size_t)(s * (K / 16) + chunk) * N + n) * 16 + p] = __uint_as_float(tf32r(W[i]));
}

// ---------------- one layer ----------------
template<int K, int N, bool IS_L0, bool ROUND>
__device__ __forceinline__ void layer_run(
    const float* __restrict__ Wp, const float* __restrict__ bg,
    const float* __restrict__ xg,
    float* __restrict__ Ys, const float* __restrict__ WcF, const float* __restrict__ XcF,
    uint32_t wcU, uint32_t xcU,
    int tid, int lane, int m_idx, int n_idx)
{
    constexpr int NT = N / 32;
    constexpr int NC = K / 16;

    float acc[4][NT][4];
#pragma unroll
    for (int f = 0; f < 4; f++)
#pragma unroll
        for (int t = 0; t < NT; t++)
#pragma unroll
            for (int j = 0; j < 4; j++) acc[f][t][j] = 0.f;

    // -------- staging lambdas --------
    auto stage = [&](int c) {
        const char* wsrc = (const char*)(Wp + (size_t)c * N * 16);
        uint32_t wdst = wcU + (uint32_t)(c % 3) * 16384u;
        for (int i = tid; i < N * 4; i += 256)
            CP_ASYNC16(wdst + (uint32_t)i * 16u, wsrc + (size_t)i * 16);
        if (IS_L0) {
            uint32_t xdst = xcU + (uint32_t)(c % 3) * 10240u;
#pragma unroll
            for (int j = 0; j < 2; j++) {
                int i = tid + j * 256;           // i < 512
                int row = i >> 2, blk = i & 3;
                const float* src = xg + (size_t)row * 98304 + c * 16 + blk * 4;
                CP_ASYNC16(xdst + (uint32_t)(row * 80 + blk * 16), src);
            }
        }
    };

    stage(0); CP_COMMIT();
    stage(1); CP_COMMIT();

    const int q = lane & 3, g4 = lane >> 2;

    for (int c = 0; c < NC; c++) {
        CP_WAIT1();
        __syncthreads();

        // ---- A fragments for this chunk ----
        float4 a0[4], a1[4];
        if (IS_L0) {
            const float* Xs = XcF + (c % 3) * 2560;
#pragma unroll
            for (int f = 0; f < 4; f++) {
                const float* p0 = Xs + (m_idx * 64 + f * 16 + g4) * 20 + q;
                const float* p1 = p0 + 8 * 20;
                a0[f].x = p0[0]; a0[f].y = p0[4]; a0[f].z = p0[8]; a0[f].w = p0[12];
                a1[f].x = p1[0]; a1[f].y = p1[4]; a1[f].z = p1[8]; a1[f].w = p1[12];
            }
        } else {
            const int colb = c * 16 + 4 * q;
#pragma unroll
            for (int f = 0; f < 4; f++) {
                const float* p0 = Ys + (m_idx * 64 + f * 16 + g4) * LDY + colb;
                a0[f] = *(const float4*)p0;
                a1[f] = *(const float4*)(p0 + 8 * LDY);
            }
        }

        // ---- MMA over N tiles ----
        const float* Ws = WcF + (c % 3) * 4096;
#pragma unroll
        for (int t = 0; t < NT; t++) {
            const int nb = n_idx * (N / 4) + t * 8 + g4;
            float4 bv = *(const float4*)(Ws + nb * 16 + 4 * q);
#pragma unroll
            for (int f = 0; f < 4; f++) {
                mma_tf32(acc[f][t],
                         __float_as_uint(a0[f].x), __float_as_uint(a1[f].x),
                         __float_as_uint(a0[f].y), __float_as_uint(a1[f].y),
                         __float_as_uint(bv.x), __float_as_uint(bv.y));
                mma_tf32(acc[f][t],
                         __float_as_uint(a0[f].z), __float_as_uint(a1[f].z),
                         __float_as_uint(a0[f].w), __float_as_uint(a1[f].w),
                         __float_as_uint(bv.z), __float_as_uint(bv.w));
            }
        }

        if (c + 2 < NC) stage(c + 2);
        CP_COMMIT();
    }
    __syncthreads();   // all MMA reads of Ys done before epilogue overwrites

    // ---- epilogue: +bias, celu, (round), permuted store to Ys ----
#pragma unroll
    for (int f = 0; f < 4; f++) {
#pragma unroll
        for (int t = 0; t < NT; t++) {
            const int r = m_idx * 64 + f * 16 + g4;
            const int cn = n_idx * (N / 4) + t * 8 + 2 * q;
            const float bv0 = __ldg(bg + cn), bv1 = __ldg(bg + cn + 1);
            float v0 = celu_f(acc[f][t][0] + bv0);
            float v1 = celu_f(acc[f][t][1] + bv1);
            float v2 = celu_f(acc[f][t][2] + bv0);
            float v3 = celu_f(acc[f][t][3] + bv1);
            if (ROUND) {
                v0 = __uint_as_float(tf32r(v0)); v1 = __uint_as_float(tf32r(v1));
                v2 = __uint_as_float(tf32r(v2)); v3 = __uint_as_float(tf32r(v3));
            }
            const int w0 = cn & 15, w1 = (cn + 1) & 15;
            const int p0 = (cn & ~15) + (((w0 & 3) << 2) | (w0 >> 2));
            const int p1 = (cn & ~15) + (((w1 & 3) << 2) | (w1 >> 2));
            Ys[r * LDY + p0] = v0;
            Ys[r * LDY + p1] = v1;
            Ys[(r + 8) * LDY + p0] = v2;
            Ys[(r + 8) * LDY + p1] = v3;
        }
    }
    __syncthreads();
}

// ---------------- fused kernel ----------------
__global__ void __launch_bounds__(256, 1)
aev_mlp_mma(const float* __restrict__ fullaev, const int* __restrict__ species,
            const float* __restrict__ b0, const float* __restrict__ b1,
            const float* __restrict__ b2,
            const float* __restrict__ W3, const float* __restrict__ b3)
{
    extern __shared__ float sm[];
    float* Ys = sm;
    const float* WcF = sm + OFF_W;
    const float* XcF = sm + OFF_X;
    const uint32_t smU = smem_u32(sm);
    const uint32_t wcU = smU + OFF_W * 4;
    const uint32_t xcU = smU + OFF_X * 4;

    const int a = blockIdx.y;
    const int bbase = blockIdx.x * 128;
    const int tid = threadIdx.x;
    const int lane = tid & 31, wid = tid >> 5;
    const int m_idx = wid >> 2, n_idx = wid & 3;
    const int s = species[a];
    const float* xg = fullaev + (size_t)bbase * 98304 + (size_t)a * 384;

    layer_run<384, 256, true,  true >(g_Wp0 + (size_t)s * (24 * 256 * 16), b0 + s * 256, xg,
                                      Ys, WcF, XcF, wcU, xcU, tid, lane, m_idx, n_idx);
    layer_run<256, 192, false, true >(g_Wp1 + (size_t)s * (16 * 192 * 16), b1 + s * 192, xg,
                                      Ys, WcF, XcF, wcU, xcU, tid, lane, m_idx, n_idx);
    layer_run<192, 160, false, false>(g_Wp2 + (size_t)s * (12 * 160 * 16), b2 + s * 160, xg,
                                      Ys, WcF, XcF, wcU, xcU, tid, lane, m_idx, n_idx);

    // ---- layer 3: dot(Y2[r, 0:160], w3) + b3, celu ----
    if (tid < 128) {
        const float* w = W3 + s * 160;
        float s0 = 0.f, s1 = 0.f, s2 = 0.f, s3 = 0.f;
        const float* yr = Ys + tid * LDY;
#pragma unroll
        for (int k = 0; k < 160; k += 4) {
            // logical cols k..k+3 -> stored perm positions
            const int gb = k & ~15;
            const int w0 = k & 15;
            const int pA = gb + (((w0 & 3) << 2) | (w0 >> 2));
            const int w1 = (k + 1) & 15, w2 = (k + 2) & 15, w3i = (k + 3) & 15;
            const int pB = gb + (((w1 & 3) << 2) | (w1 >> 2));
            const int pC = gb + (((w2 & 3) << 2) | (w2 >> 2));
            const int pD = gb + (((w3i & 3) << 2) | (w3i >> 2));
            s0 = fmaf(yr[pA], __ldg(w + k + 0), s0);
            s1 = fmaf(yr[pB], __ldg(w + k + 1), s1);
            s2 = fmaf(yr[pC], __ldg(w + k + 2), s2);
            s3 = fmaf(yr[pD], __ldg(w + k + 3), s3);
        }
        float acc = ((s0 + s1) + (s2 + s3)) + __ldg(b3 + s);
        g_partial[(size_t)a * 1024 + bbase + tid] = celu_f(acc);
    }
}

// ---------------- deterministic two-stage reduction ----------------
__global__ void reduce1() {
    int b = blockIdx.x * 256 + threadIdx.x;
    int ag = blockIdx.y;
    float acc = 0.f;
#pragma unroll
    for (int i = 0; i < 32; i++) acc += g_partial[(size_t)(ag * 32 + i) * 1024 + b];
    g_red[ag * 1024 + b] = acc;
}
__global__ void reduce2(float* __restrict__ out) {
    int b = blockIdx.x * 256 + threadIdx.x;
    float acc = 0.f;
#pragma unroll
    for (int g = 0; g < 8; g++) acc += g_red[g * 1024 + b];
    out[b] = acc;
}

extern "C" void kernel_launch(void* const* d_in, const int* in_sizes, int n_in,
                              void* d_out, int out_size) {
    const float* fullaev = (const float*)d_in[0];
    const int*   species = (const int*)d_in[1];
    const float* W0 = (const float*)d_in[2];
    const float* b0 = (const float*)d_in[3];
    const float* W1 = (const float*)d_in[4];
    const float* b1 = (const float*)d_in[5];
    const float* W2 = (const float*)d_in[6];
    const float* b2 = (const float*)d_in[7];
    const float* W3 = (const float*)d_in[8];
    const float* b3 = (const float*)d_in[9];

    prep_w<384, 256, 0><<<(4 * 384 * 256 + 255) / 256, 256>>>(W0);
    prep_w<256, 192, 1><<<(4 * 256 * 192 + 255) / 256, 256>>>(W1);
    prep_w<192, 160, 2><<<(4 * 192 * 160 + 255) / 256, 256>>>(W2);

    cudaFuncSetAttribute(aev_mlp_mma, cudaFuncAttributeMaxDynamicSharedMemorySize, SMEM_BYTES);
    dim3 grid(8, 256);   // (B-tiles of 128, atoms)
    aev_mlp_mma<<<grid, 256, SMEM_BYTES>>>(fullaev, species, b0, b1, b2, W3, b3);

    reduce1<<<dim3(4, 8), 256>>>();
    reduce2<<<4, 256>>>((float*)d_out);
}

// round 5
// speedup vs baseline: 1.2213x; 1.2213x over previous
#include <cuda_runtime.h>
#include <cstdint>
#include <math.h>

#define ALPHA_CELU 0.1f

// ---------------- device scratch ----------------
__device__ float g_Wp0[4 * 24 * 256 * 16];   // [s][chunk][n][16 perm k]
__device__ float g_Wp1[4 * 16 * 192 * 16];
__device__ float g_Wp2[4 * 12 * 160 * 16];
__device__ float g_partial[256 * 1024];      // [atom][b]
__device__ float g_red[8 * 1024];

// ---------------- helpers ----------------
__device__ __forceinline__ float celu_f(float x) {
    return x > 0.f ? x : ALPHA_CELU * expm1f(x * (1.f / ALPHA_CELU));
}
__device__ __forceinline__ uint32_t tf32r(float x) {   // RNA round to tf32
    uint32_t u;
    asm("cvt.rna.tf32.f32 %0, %1;" : "=r"(u) : "f"(x));
    return u;
}
__device__ __forceinline__ float tf32rf(float x) { return __uint_as_float(tf32r(x)); }
__device__ __forceinline__ uint32_t smem_u32(const void* p) {
    uint32_t a;
    asm("{ .reg .u64 t; cvta.to.shared.u64 t, %1; cvt.u32.u64 %0, t; }" : "=r"(a) : "l"(p));
    return a;
}
__device__ __forceinline__ void mma_tf32(float c[4],
                                         uint32_t a0, uint32_t a1, uint32_t a2, uint32_t a3,
                                         uint32_t b0, uint32_t b1) {
    asm volatile("mma.sync.aligned.m16n8k8.row.col.f32.tf32.tf32.f32 "
                 "{%0,%1,%2,%3}, {%4,%5,%6,%7}, {%8,%9}, {%0,%1,%2,%3};"
                 : "+f"(c[0]), "+f"(c[1]), "+f"(c[2]), "+f"(c[3])
                 : "r"(a0), "r"(a1), "r"(a2), "r"(a3), "r"(b0), "r"(b1));
}
#define CP_ASYNC16(dst, src) \
    asm volatile("cp.async.ca.shared.global [%0], [%1], 16;" :: "r"(dst), "l"(src))
#define CP_COMMIT() asm volatile("cp.async.commit_group;" ::: "memory")
#define CP_WAIT1()  asm volatile("cp.async.wait_group 1;" ::: "memory")

// ---------------- smem layout (floats) ----------------
#define LDY 272
#define OFF_W (128 * LDY)               // 34816
#define OFF_X (OFF_W + 3 * 4096)        // 47104
#define SMEM_FLOATS (OFF_X + 3 * 2560)  // 54784
#define SMEM_BYTES (SMEM_FLOATS * 4)    // 219136

// ---------------- weight prep: [S,K,N] -> [s][k/16][n][perm(k&15)] tf32 ----------------
template<int K, int N, int WHICH>
__global__ void prep_w(const float* __restrict__ W) {
    int i = blockIdx.x * blockDim.x + threadIdx.x;
    if (i >= 4 * K * N) return;
    float* dst = (WHICH == 0) ? g_Wp0 : (WHICH == 1) ? g_Wp1 : g_Wp2;
    int n = i % N, k = (i / N) % K, s = i / (N * K);
    int chunk = k >> 4, w = k & 15;
    int p = ((w & 3) << 2) | (w >> 2);
    dst[((size_t)(s * (K / 16) + chunk) * N + n) * 16 + p] = __uint_as_float(tf32r(W[i]));
}

// ---------------- one layer (512 threads, warp grid 4m x 4n, warp tile 32 x N/4) ----------------
template<int K, int N, bool IS_L0, bool ROUND>
__device__ __forceinline__ void layer_run(
    const float* __restrict__ Wp, const float* __restrict__ bg,
    const float* __restrict__ xg,
    float* __restrict__ Ys, const float* __restrict__ WcF, const float* __restrict__ XcF,
    uint32_t wcU, uint32_t xcU,
    int tid, int lane, int m_idx, int n_idx)
{
    constexpr int NT = N / 32;          // n8 tiles per warp (8 / 6 / 5)
    constexpr int NC = K / 16;

    float acc[2][NT][4];
#pragma unroll
    for (int f = 0; f < 2; f++)
#pragma unroll
        for (int t = 0; t < NT; t++)
#pragma unroll
            for (int j = 0; j < 4; j++) acc[f][t][j] = 0.f;

    auto stage = [&](int c) {
        const char* wsrc = (const char*)(Wp + (size_t)c * N * 16);
        uint32_t wdst = wcU + (uint32_t)(c % 3) * 16384u;
        for (int i = tid; i < N * 4; i += 512)
            CP_ASYNC16(wdst + (uint32_t)i * 16u, wsrc + (size_t)i * 16);
        if (IS_L0) {
            uint32_t xdst = xcU + (uint32_t)(c % 3) * 10240u;
            int row = tid >> 2, blk = tid & 3;          // 512 threads = 512 float4s
            const float* src = xg + (size_t)row * 98304 + c * 16 + blk * 4;
            CP_ASYNC16(xdst + (uint32_t)(row * 80 + blk * 16), src);
        }
    };

    stage(0); CP_COMMIT();
    stage(1); CP_COMMIT();

    const int q = lane & 3, g4 = lane >> 2;

    for (int c = 0; c < NC; c++) {
        CP_WAIT1();
        __syncthreads();

        // ---- A fragments ----
        float4 a0[2], a1[2];
        if (IS_L0) {
            const float* Xs = XcF + (c % 3) * 2560;
#pragma unroll
            for (int f = 0; f < 2; f++) {
                const float* p0 = Xs + (m_idx * 32 + f * 16 + g4) * 20 + q;
                const float* p1 = p0 + 8 * 20;
                // RNA-round X fragments (cp.async staged raw fp32)
                a0[f].x = tf32rf(p0[0]);  a0[f].y = tf32rf(p0[4]);
                a0[f].z = tf32rf(p0[8]);  a0[f].w = tf32rf(p0[12]);
                a1[f].x = tf32rf(p1[0]);  a1[f].y = tf32rf(p1[4]);
                a1[f].z = tf32rf(p1[8]);  a1[f].w = tf32rf(p1[12]);
            }
        } else {
            const int colb = c * 16 + 4 * q;
#pragma unroll
            for (int f = 0; f < 2; f++) {
                const float* p0 = Ys + (m_idx * 32 + f * 16 + g4) * LDY + colb;
                a0[f] = *(const float4*)p0;
                a1[f] = *(const float4*)(p0 + 8 * LDY);
            }
        }

        // ---- MMA over N tiles ----
        const float* Ws = WcF + (c % 3) * 4096;
#pragma unroll
        for (int t = 0; t < NT; t++) {
            const int nb = n_idx * (N / 4) + t * 8 + g4;
            float4 bv = *(const float4*)(Ws + nb * 16 + 4 * q);
#pragma unroll
            for (int f = 0; f < 2; f++) {
                mma_tf32(acc[f][t],
                         __float_as_uint(a0[f].x), __float_as_uint(a1[f].x),
                         __float_as_uint(a0[f].y), __float_as_uint(a1[f].y),
                         __float_as_uint(bv.x), __float_as_uint(bv.y));
                mma_tf32(acc[f][t],
                         __float_as_uint(a0[f].z), __float_as_uint(a1[f].z),
                         __float_as_uint(a0[f].w), __float_as_uint(a1[f].w),
                         __float_as_uint(bv.z), __float_as_uint(bv.w));
            }
        }

        if (c + 2 < NC) stage(c + 2);
        CP_COMMIT();
    }
    __syncthreads();   // all MMA reads of Ys done before epilogue overwrites

    // ---- epilogue: +bias, celu, (round), permuted store to Ys ----
#pragma unroll
    for (int f = 0; f < 2; f++) {
#pragma unroll
        for (int t = 0; t < NT; t++) {
            const int r = m_idx * 32 + f * 16 + g4;
            const int cn = n_idx * (N / 4) + t * 8 + 2 * q;
            const float bv0 = __ldg(bg + cn), bv1 = __ldg(bg + cn + 1);
            float v0 = celu_f(acc[f][t][0] + bv0);
            float v1 = celu_f(acc[f][t][1] + bv1);
            float v2 = celu_f(acc[f][t][2] + bv0);
            float v3 = celu_f(acc[f][t][3] + bv1);
            if (ROUND) {
                v0 = tf32rf(v0); v1 = tf32rf(v1);
                v2 = tf32rf(v2); v3 = tf32rf(v3);
            }
            const int w0 = cn & 15, w1 = (cn + 1) & 15;
            const int p0 = (cn & ~15) + (((w0 & 3) << 2) | (w0 >> 2));
            const int p1 = (cn & ~15) + (((w1 & 3) << 2) | (w1 >> 2));
            Ys[r * LDY + p0] = v0;
            Ys[r * LDY + p1] = v1;
            Ys[(r + 8) * LDY + p0] = v2;
            Ys[(r + 8) * LDY + p1] = v3;
        }
    }
    __syncthreads();
}

// ---------------- fused kernel ----------------
__global__ void __launch_bounds__(512, 1)
aev_mlp_mma(const float* __restrict__ fullaev, const int* __restrict__ species,
            const float* __restrict__ b0, const float* __restrict__ b1,
            const float* __restrict__ b2,
            const float* __restrict__ W3, const float* __restrict__ b3)
{
    extern __shared__ float sm[];
    float* Ys = sm;
    const float* WcF = sm + OFF_W;
    const float* XcF = sm + OFF_X;
    const uint32_t smU = smem_u32(sm);
    const uint32_t wcU = smU + OFF_W * 4;
    const uint32_t xcU = smU + OFF_X * 4;

    const int a = blockIdx.y;
    const int bbase = blockIdx.x * 128;
    const int tid = threadIdx.x;
    const int lane = tid & 31, wid = tid >> 5;
    const int m_idx = wid >> 2, n_idx = wid & 3;
    const int s = species[a];
    const float* xg = fullaev + (size_t)bbase * 98304 + (size_t)a * 384;

    layer_run<384, 256, true,  true >(g_Wp0 + (size_t)s * (24 * 256 * 16), b0 + s * 256, xg,
                                      Ys, WcF, XcF, wcU, xcU, tid, lane, m_idx, n_idx);
    layer_run<256, 192, false, true >(g_Wp1 + (size_t)s * (16 * 192 * 16), b1 + s * 192, xg,
                                      Ys, WcF, XcF, wcU, xcU, tid, lane, m_idx, n_idx);
    layer_run<192, 160, false, false>(g_Wp2 + (size_t)s * (12 * 160 * 16), b2 + s * 160, xg,
                                      Ys, WcF, XcF, wcU, xcU, tid, lane, m_idx, n_idx);

    // ---- layer 3: dot(Y2[r, 0:160], w3) + b3, celu ----
    if (tid < 128) {
        const float* w = W3 + s * 160;
        float s0 = 0.f, s1 = 0.f, s2 = 0.f, s3 = 0.f;
        const float* yr = Ys + tid * LDY;
#pragma unroll
        for (int k = 0; k < 160; k += 4) {
            const int gb = k & ~15;
            const int w0 = k & 15;
            const int pA = gb + (((w0 & 3) << 2) | (w0 >> 2));
            const int w1 = (k + 1) & 15, w2 = (k + 2) & 15, w3i = (k + 3) & 15;
            const int pB = gb + (((w1 & 3) << 2) | (w1 >> 2));
            const int pC = gb + (((w2 & 3) << 2) | (w2 >> 2));
            const int pD = gb + (((w3i & 3) << 2) | (w3i >> 2));
            s0 = fmaf(yr[pA], __ldg(w + k + 0), s0);
            s1 = fmaf(yr[pB], __ldg(w + k + 1), s1);
            s2 = fmaf(yr[pC], __ldg(w + k + 2), s2);
            s3 = fmaf(yr[pD], __ldg(w + k + 3), s3);
        }
        float acc = ((s0 + s1) + (s2 + s3)) + __ldg(b3 + s);
        g_partial[(size_t)a * 1024 + bbase + tid] = celu_f(acc);
    }
}

// ---------------- deterministic two-stage reduction ----------------
__global__ void reduce1() {
    int b = blockIdx.x * 256 + threadIdx.x;
    int ag = blockIdx.y;
    float acc = 0.f;
#pragma unroll
    for (int i = 0; i < 32; i++) acc += g_partial[(size_t)(ag * 32 + i) * 1024 + b];
    g_red[ag * 1024 + b] = acc;
}
__global__ void reduce2(float* __restrict__ out) {
    int b = blockIdx.x * 256 + threadIdx.x;
    float acc = 0.f;
#pragma unroll
    for (int g = 0; g < 8; g++) acc += g_red[g * 1024 + b];
    out[b] = acc;
}

extern "C" void kernel_launch(void* const* d_in, const int* in_sizes, int n_in,
                              void* d_out, int out_size) {
    const float* fullaev = (const float*)d_in[0];
    const int*   species = (const int*)d_in[1];
    const float* W0 = (const float*)d_in[2];
    const float* b0 = (const float*)d_in[3];
    const float* W1 = (const float*)d_in[4];
    const float* b1 = (const float*)d_in[5];
    const float* W2 = (const float*)d_in[6];
    const float* b2 = (const float*)d_in[7];
    const float* W3 = (const float*)d_in[8];
    const float* b3 = (const float*)d_in[9];

    prep_w<384, 256, 0><<<(4 * 384 * 256 + 255) / 256, 256>>>(W0);
    prep_w<256, 192, 1><<<(4 * 256 * 192 + 255) / 256, 256>>>(W1);
    prep_w<192, 160, 2><<<(4 * 192 * 160 + 255) / 256, 256>>>(W2);

    cudaFuncSetAttribute(aev_mlp_mma, cudaFuncAttributeMaxDynamicSharedMemorySize, SMEM_BYTES);
    dim3 grid(8, 256);   // (B-tiles of 128, atoms)
    aev_mlp_mma<<<grid, 512, SMEM_BYTES>>>(fullaev, species, b0, b1, b2, W3, b3);

    reduce1<<<dim3(4, 8), 256>>>();
    reduce2<<<4, 256>>>((float*)d_out);
}

// round 6
// speedup vs baseline: 1.3295x; 1.0886x over previous
#include <cuda_runtime.h>
#include <cstdint>
#include <math.h>

#define ALPHA_CELU 0.1f

// ---------------- device scratch ----------------
__device__ float g_Wp0[4 * 24 * 256 * 16];   // [s][chunk][n][16 perm k]
__device__ float g_Wp1[4 * 16 * 192 * 16];
__device__ float g_Wp2[4 * 12 * 160 * 16];
__device__ float g_partial[256 * 1024];      // [atom][b]
__device__ float g_red[8 * 1024];

// ---------------- helpers ----------------
__device__ __forceinline__ float celu_f(float x) {
    return x > 0.f ? x : ALPHA_CELU * expm1f(x * (1.f / ALPHA_CELU));
}
__device__ __forceinline__ uint32_t tf32r(float x) {   // RNA round to tf32
    uint32_t u;
    asm("cvt.rna.tf32.f32 %0, %1;" : "=r"(u) : "f"(x));
    return u;
}
__device__ __forceinline__ float tf32rf(float x) { return __uint_as_float(tf32r(x)); }
__device__ __forceinline__ uint32_t smem_u32(const void* p) {
    uint32_t a;
    asm("{ .reg .u64 t; cvta.to.shared.u64 t, %1; cvt.u32.u64 %0, t; }" : "=r"(a) : "l"(p));
    return a;
}
__device__ __forceinline__ void mma_tf32(float c[4],
                                         uint32_t a0, uint32_t a1, uint32_t a2, uint32_t a3,
                                         uint32_t b0, uint32_t b1) {
    asm volatile("mma.sync.aligned.m16n8k8.row.col.f32.tf32.tf32.f32 "
                 "{%0,%1,%2,%3}, {%4,%5,%6,%7}, {%8,%9}, {%0,%1,%2,%3};"
                 : "+f"(c[0]), "+f"(c[1]), "+f"(c[2]), "+f"(c[3])
                 : "r"(a0), "r"(a1), "r"(a2), "r"(a3), "r"(b0), "r"(b1));
}
#define CP_ASYNC16(dst, src) \
    asm volatile("cp.async.ca.shared.global [%0], [%1], 16;" :: "r"(dst), "l"(src))
#define CP_COMMIT() asm volatile("cp.async.commit_group;" ::: "memory")
#define CP_WAIT1()  asm volatile("cp.async.wait_group 1;" ::: "memory")

// ---------------- smem layout (floats) ----------------
// Ys: 128 x 272 (v4-phase conflict-free).  X ring (L0 only) OVERLAYS Ys[0..10240):
// X reads all complete before the L0 epilogue writes Ys.  W ring after Ys.
#define LDY 272
#define OFF_W (128 * LDY)                 // 34816 floats
#define SMEM_FLOATS (OFF_W + 4 * 4096)    // 51200 floats
#define SMEM_BYTES (SMEM_FLOATS * 4)      // 204800 B

// ---------------- weight prep: [S,K,N] -> [s][k/16][n][perm(k&15)] tf32 ----------------
template<int K, int N, int WHICH>
__global__ void prep_w(const float* __restrict__ W) {
    int i = blockIdx.x * blockDim.x + threadIdx.x;
    if (i >= 4 * K * N) return;
    float* dst = (WHICH == 0) ? g_Wp0 : (WHICH == 1) ? g_Wp1 : g_Wp2;
    int n = i % N, k = (i / N) % K, s = i / (N * K);
    int chunk = k >> 4, w = k & 15;
    int p = ((w & 3) << 2) | (w >> 2);
    dst[((size_t)(s * (K / 16) + chunk) * N + n) * 16 + p] = __uint_as_float(tf32r(W[i]));
}

// ---------------- one layer (512 threads, warp grid 4m x 4n, warp tile 32 x N/4) ----------------
template<int K, int N, bool IS_L0, bool ROUND>
__device__ __forceinline__ void layer_run(
    const float* __restrict__ Wp, const float* __restrict__ bg,
    const float* __restrict__ xg,
    float* __restrict__ Ys, const float* __restrict__ WcF, const float* __restrict__ XcF,
    uint32_t wcU, uint32_t xcU,
    int tid, int lane, int m_idx, int n_idx)
{
    constexpr int NT = N / 32;          // n8 tiles per warp (8 / 6 / 5)
    constexpr int NC = K / 16;
    constexpr int WI = (N * 4 + 511) / 512;   // W float4s per thread per chunk

    float acc[2][NT][4];
#pragma unroll
    for (int f = 0; f < 2; f++)
#pragma unroll
        for (int t = 0; t < NT; t++)
#pragma unroll
            for (int j = 0; j < 4; j++) acc[f][t][j] = 0.f;

    const int xrow = tid >> 2, xblk = tid & 3;

    auto stage = [&](int c) {
        const char* wsrc = (const char*)(Wp + (size_t)c * N * 16);
        const uint32_t wdst = wcU + (uint32_t)(c & 3) * 16384u;
#pragma unroll
        for (int j = 0; j < WI; j++) {
            int i = tid + j * 512;
            if ((N * 4) % 512 == 0 || i < N * 4)
                CP_ASYNC16(wdst + (uint32_t)i * 16u, wsrc + (size_t)i * 16);
        }
        if (IS_L0) {
            const uint32_t xdst = xcU + (uint32_t)(c & 3) * 10240u;
            const float* src = xg + (size_t)xrow * 98304 + c * 16 + xblk * 4;
            CP_ASYNC16(xdst + (uint32_t)(xrow * 80 + xblk * 16), src);
        }
    };

    stage(0); CP_COMMIT();
    stage(1); CP_COMMIT();

    const int q = lane & 3, g4 = lane >> 2;

#pragma unroll 4
    for (int c = 0; c < NC; c++) {
        CP_WAIT1();
        __syncthreads();

        // ---- A fragments ----
        float4 a0[2], a1[2];
        if (IS_L0) {
            const float* Xs = XcF + (c & 3) * 2560;
#pragma unroll
            for (int f = 0; f < 2; f++) {
                const float* p0 = Xs + (m_idx * 32 + f * 16 + g4) * 20 + q;
                const float* p1 = p0 + 8 * 20;
                a0[f].x = tf32rf(p0[0]);  a0[f].y = tf32rf(p0[4]);
                a0[f].z = tf32rf(p0[8]);  a0[f].w = tf32rf(p0[12]);
                a1[f].x = tf32rf(p1[0]);  a1[f].y = tf32rf(p1[4]);
                a1[f].z = tf32rf(p1[8]);  a1[f].w = tf32rf(p1[12]);
            }
        } else {
            const int colb = c * 16 + 4 * q;
#pragma unroll
            for (int f = 0; f < 2; f++) {
                const float* p0 = Ys + (m_idx * 32 + f * 16 + g4) * LDY + colb;
                a0[f] = *(const float4*)p0;
                a1[f] = *(const float4*)(p0 + 8 * LDY);
            }
        }

        // ---- MMA over N tiles ----
        const float* Ws = WcF + (c & 3) * 4096;
#pragma unroll
        for (int t = 0; t < NT; t++) {
            const int nb = n_idx * (N / 4) + t * 8 + g4;
            float4 bv = *(const float4*)(Ws + nb * 16 + 4 * q);
#pragma unroll
            for (int f = 0; f < 2; f++) {
                mma_tf32(acc[f][t],
                         __float_as_uint(a0[f].x), __float_as_uint(a1[f].x),
                         __float_as_uint(a0[f].y), __float_as_uint(a1[f].y),
                         __float_as_uint(bv.x), __float_as_uint(bv.y));
                mma_tf32(acc[f][t],
                         __float_as_uint(a0[f].z), __float_as_uint(a1[f].z),
                         __float_as_uint(a0[f].w), __float_as_uint(a1[f].w),
                         __float_as_uint(bv.z), __float_as_uint(bv.w));
            }
        }

        if (c + 2 < NC) stage(c + 2);
        CP_COMMIT();
    }
    __syncthreads();   // all MMA reads done before epilogue overwrites Ys

    // ---- epilogue: +bias, celu, (round), permuted store to Ys ----
#pragma unroll
    for (int f = 0; f < 2; f++) {
#pragma unroll
        for (int t = 0; t < NT; t++) {
            const int r = m_idx * 32 + f * 16 + g4;
            const int cn = n_idx * (N / 4) + t * 8 + 2 * q;
            const float bv0 = __ldg(bg + cn), bv1 = __ldg(bg + cn + 1);
            float v0 = celu_f(acc[f][t][0] + bv0);
            float v1 = celu_f(acc[f][t][1] + bv1);
            float v2 = celu_f(acc[f][t][2] + bv0);
            float v3 = celu_f(acc[f][t][3] + bv1);
            if (ROUND) {
                v0 = tf32rf(v0); v1 = tf32rf(v1);
                v2 = tf32rf(v2); v3 = tf32rf(v3);
            }
            const int w0 = cn & 15, w1 = (cn + 1) & 15;
            const int p0 = (cn & ~15) + (((w0 & 3) << 2) | (w0 >> 2));
            const int p1 = (cn & ~15) + (((w1 & 3) << 2) | (w1 >> 2));
            Ys[r * LDY + p0] = v0;
            Ys[r * LDY + p1] = v1;
            Ys[(r + 8) * LDY + p0] = v2;
            Ys[(r + 8) * LDY + p1] = v3;
        }
    }
    __syncthreads();
}

// ---------------- fused kernel ----------------
__global__ void __launch_bounds__(512, 1)
aev_mlp_mma(const float* __restrict__ fullaev, const int* __restrict__ species,
            const float* __restrict__ b0, const float* __restrict__ b1,
            const float* __restrict__ b2,
            const float* __restrict__ W3, const float* __restrict__ b3)
{
    extern __shared__ float sm[];
    float* Ys = sm;
    const float* WcF = sm + OFF_W;
    const float* XcF = sm;                  // X ring overlays Ys during L0
    const uint32_t smU = smem_u32(sm);
    const uint32_t wcU = smU + OFF_W * 4;
    const uint32_t xcU = smU;

    const int a = blockIdx.y;
    const int bbase = blockIdx.x * 128;
    const int tid = threadIdx.x;
    const int lane = tid & 31, wid = tid >> 5;
    const int m_idx = wid >> 2, n_idx = wid & 3;
    const int s = species[a];
    const float* xg = fullaev + (size_t)bbase * 98304 + (size_t)a * 384;

    layer_run<384, 256, true,  true >(g_Wp0 + (size_t)s * (24 * 256 * 16), b0 + s * 256, xg,
                                      Ys, WcF, XcF, wcU, xcU, tid, lane, m_idx, n_idx);
    layer_run<256, 192, false, true >(g_Wp1 + (size_t)s * (16 * 192 * 16), b1 + s * 192, xg,
                                      Ys, WcF, XcF, wcU, xcU, tid, lane, m_idx, n_idx);
    layer_run<192, 160, false, false>(g_Wp2 + (size_t)s * (12 * 160 * 16), b2 + s * 160, xg,
                                      Ys, WcF, XcF, wcU, xcU, tid, lane, m_idx, n_idx);

    // ---- layer 3: dot(Y2[r, 0:160], w3) + b3, celu ----
    if (tid < 128) {
        const float* w = W3 + s * 160;
        float s0 = 0.f, s1 = 0.f, s2 = 0.f, s3 = 0.f;
        const float* yr = Ys + tid * LDY;
#pragma unroll
        for (int k = 0; k < 160; k += 4) {
            const int gb = k & ~15;
            const int w0 = k & 15;
            const int pA = gb + (((w0 & 3) << 2) | (w0 >> 2));
            const int w1 = (k + 1) & 15, w2 = (k + 2) & 15, w3i = (k + 3) & 15;
            const int pB = gb + (((w1 & 3) << 2) | (w1 >> 2));
            const int pC = gb + (((w2 & 3) << 2) | (w2 >> 2));
            const int pD = gb + (((w3i & 3) << 2) | (w3i >> 2));
            s0 = fmaf(yr[pA], __ldg(w + k + 0), s0);
            s1 = fmaf(yr[pB], __ldg(w + k + 1), s1);
            s2 = fmaf(yr[pC], __ldg(w + k + 2), s2);
            s3 = fmaf(yr[pD], __ldg(w + k + 3), s3);
        }
        float acc = ((s0 + s1) + (s2 + s3)) + __ldg(b3 + s);
        g_partial[(size_t)a * 1024 + bbase + tid] = celu_f(acc);
    }
}

// ---------------- deterministic two-stage reduction ----------------
__global__ void reduce1() {
    int b = blockIdx.x * 256 + threadIdx.x;
    int ag = blockIdx.y;
    float acc = 0.f;
#pragma unroll
    for (int i = 0; i < 32; i++) acc += g_partial[(size_t)(ag * 32 + i) * 1024 + b];
    g_red[ag * 1024 + b] = acc;
}
__global__ void reduce2(float* __restrict__ out) {
    int b = blockIdx.x * 256 + threadIdx.x;
    float acc = 0.f;
#pragma unroll
    for (int g = 0; g < 8; g++) acc += g_red[g * 1024 + b];
    out[b] = acc;
}

extern "C" void kernel_launch(void* const* d_in, const int* in_sizes, int n_in,
                              void* d_out, int out_size) {
    const float* fullaev = (const float*)d_in[0];
    const int*   species = (const int*)d_in[1];
    const float* W0 = (const float*)d_in[2];
    const float* b0 = (const float*)d_in[3];
    const float* W1 = (const float*)d_in[4];
    const float* b1 = (const float*)d_in[5];
    const float* W2 = (const float*)d_in[6];
    const float* b2 = (const float*)d_in[7];
    const float* W3 = (const float*)d_in[8];
    const float* b3 = (const float*)d_in[9];

    prep_w<384, 256, 0><<<(4 * 384 * 256 + 255) / 256, 256>>>(W0);
    prep_w<256, 192, 1><<<(4 * 256 * 192 + 255) / 256, 256>>>(W1);
    prep_w<192, 160, 2><<<(4 * 192 * 160 + 255) / 256, 256>>>(W2);

    cudaFuncSetAttribute(aev_mlp_mma, cudaFuncAttributeMaxDynamicSharedMemorySize, SMEM_BYTES);
    dim3 grid(8, 256);   // (B-tiles of 128, atoms)
    aev_mlp_mma<<<grid, 512, SMEM_BYTES>>>(fullaev, species, b0, b1, b2, W3, b3);

    reduce1<<<dim3(4, 8), 256>>>();
    reduce2<<<4, 256>>>((float*)d_out);
}

// round 9
// speedup vs baseline: 1.5302x; 1.1510x over previous
#include <cuda_runtime.h>
#include <cstdint>
#include <math.h>

#define ALPHA_CELU 0.1f

// ---------------- device scratch ----------------
__device__ float g_Wp0[4 * 24 * 256 * 16];   // [s][chunk][n][16 perm k]
__device__ float g_Wp1[4 * 16 * 192 * 16];
__device__ float g_Wp2[4 * 12 * 160 * 16];
__device__ float g_partial[256 * 1024];      // [atom][b]
__device__ float g_red[8 * 1024];

// ---------------- helpers ----------------
// Branchless CELU: max(x,0) + min(0, alpha*(exp(x/alpha)-1)).
// __expf = MUFU.EX2 path; cancellation near x->0- is ~1e-9 absolute (harmless).
__device__ __forceinline__ float celu_f(float x) {
    float e = __expf(x * (1.f / ALPHA_CELU));
    return fmaxf(x, 0.f) + fminf(0.f, ALPHA_CELU * (e - 1.f));
}
__device__ __forceinline__ uint32_t tf32r(float x) {   // RNA round to tf32
    uint32_t u;
    asm("cvt.rna.tf32.f32 %0, %1;" : "=r"(u) : "f"(x));
    return u;
}
__device__ __forceinline__ float tf32rf(float x) { return __uint_as_float(tf32r(x)); }
__device__ __forceinline__ uint32_t smem_u32(const void* p) {
    uint32_t a;
    asm("{ .reg .u64 t; cvta.to.shared.u64 t, %1; cvt.u32.u64 %0, t; }" : "=r"(a) : "l"(p));
    return a;
}
__device__ __forceinline__ void mma_tf32(float c[4],
                                         uint32_t a0, uint32_t a1, uint32_t a2, uint32_t a3,
                                         uint32_t b0, uint32_t b1) {
    asm volatile("mma.sync.aligned.m16n8k8.row.col.f32.tf32.tf32.f32 "
                 "{%0,%1,%2,%3}, {%4,%5,%6,%7}, {%8,%9}, {%0,%1,%2,%3};"
                 : "+f"(c[0]), "+f"(c[1]), "+f"(c[2]), "+f"(c[3])
                 : "r"(a0), "r"(a1), "r"(a2), "r"(a3), "r"(b0), "r"(b1));
}
#define CP_ASYNC16(dst, src) \
    asm volatile("cp.async.ca.shared.global [%0], [%1], 16;" :: "r"(dst), "l"(src))
#define CP_COMMIT() asm volatile("cp.async.commit_group;" ::: "memory")
#define CP_WAIT2()  asm volatile("cp.async.wait_group 2;" ::: "memory")

// ---------------- smem layout (floats) ----------------
// Ys: 128 x 272.  X ring (L0 only, 4 slots x 2560 floats) OVERLAYS Ys.
// W ring: 4 slots x 4096 floats after Ys.
#define LDY 272
#define OFF_W (128 * LDY)                 // 34816 floats
#define SMEM_FLOATS (OFF_W + 4 * 4096)    // 51200 floats
#define SMEM_BYTES (SMEM_FLOATS * 4)      // 204800 B

// ---------------- weight prep: [S,K,N] -> [s][k/16][n][perm(k&15)] tf32 ----------------
template<int K, int N, int WHICH>
__global__ void prep_w(const float* __restrict__ W) {
    int i = blockIdx.x * blockDim.x + threadIdx.x;
    if (i >= 4 * K * N) return;
    float* dst = (WHICH == 0) ? g_Wp0 : (WHICH == 1) ? g_Wp1 : g_Wp2;
    int n = i % N, k = (i / N) % K, s = i / (N * K);
    int chunk = k >> 4, w = k & 15;
    int p = ((w & 3) << 2) | (w >> 2);
    dst[((size_t)(s * (K / 16) + chunk) * N + n) * 16 + p] = __uint_as_float(tf32r(W[i]));
}

// ---------------- one layer (512 threads, warp grid 4m x 4n, warp tile 32 x N/4) ----------------
template<int K, int N, bool IS_L0, bool ROUND>
__device__ __forceinline__ void layer_run(
    const float* __restrict__ Wp, const float* __restrict__ bg,
    const float* __restrict__ xg,
    float* __restrict__ Ys, const float* __restrict__ WcF, const float* __restrict__ XcF,
    uint32_t wcU, uint32_t xcU,
    int tid, int lane, int m_idx, int n_idx)
{
    constexpr int NT = N / 32;                // n8 tiles per warp (8 / 6 / 5)
    constexpr int NC = K / 16;
    constexpr int WI = (N * 4 + 511) / 512;   // W float4s per thread per chunk

    float acc[2][NT][4];
#pragma unroll
    for (int f = 0; f < 2; f++)
#pragma unroll
        for (int t = 0; t < NT; t++)
#pragma unroll
            for (int j = 0; j < 4; j++) acc[f][t][j] = 0.f;

    const int xrow = tid >> 2, xblk = tid & 3;   // 512 thr = 512 float4 = 128 rows x 4

    auto stage = [&](int c) {
        const char* wsrc = (const char*)(Wp + (size_t)c * N * 16);
        const uint32_t wdst = wcU + (uint32_t)(c & 3) * 16384u;
#pragma unroll
        for (int j = 0; j < WI; j++) {
            int i = tid + j * 512;
            if ((N * 4) % 512 == 0 || i < N * 4)
                CP_ASYNC16(wdst + (uint32_t)i * 16u, wsrc + (size_t)i * 16);
        }
        if (IS_L0) {
            const uint32_t xdst = xcU + (uint32_t)(c & 3) * 10240u;
            const float* src = xg + (size_t)xrow * 98304 + c * 16 + xblk * 4;
            CP_ASYNC16(xdst + (uint32_t)(xrow * 80 + xblk * 16), src);
        }
    };

    // depth-3 pipeline prologue
    stage(0); CP_COMMIT();
    stage(1); CP_COMMIT();
    stage(2); CP_COMMIT();

    const int q = lane & 3, g4 = lane >> 2;

#pragma unroll 4
    for (int c = 0; c < NC; c++) {
        CP_WAIT2();                 // with unconditional per-iter commits, guarantees chunk c landed
        __syncthreads();            // publish chunk c; all reads of chunk c-1 complete

        // ---- A fragments ----
        float4 a0[2], a1[2];
        if (IS_L0) {
            const float* Xs = XcF + (c & 3) * 2560;
#pragma unroll
            for (int f = 0; f < 2; f++) {
                const float* p0 = Xs + (m_idx * 32 + f * 16 + g4) * 20 + q;
                const float* p1 = p0 + 8 * 20;
                a0[f].x = tf32rf(p0[0]);  a0[f].y = tf32rf(p0[4]);
                a0[f].z = tf32rf(p0[8]);  a0[f].w = tf32rf(p0[12]);
                a1[f].x = tf32rf(p1[0]);  a1[f].y = tf32rf(p1[4]);
                a1[f].z = tf32rf(p1[8]);  a1[f].w = tf32rf(p1[12]);
            }
        } else {
            const int colb = c * 16 + 4 * q;
#pragma unroll
            for (int f = 0; f < 2; f++) {
                const float* p0 = Ys + (m_idx * 32 + f * 16 + g4) * LDY + colb;
                a0[f] = *(const float4*)p0;
                a1[f] = *(const float4*)(p0 + 8 * LDY);
            }
        }

        // ---- MMA over N tiles ----
        const float* Ws = WcF + (c & 3) * 4096;
#pragma unroll
        for (int t = 0; t < NT; t++) {
            const int nb = n_idx * (N / 4) + t * 8 + g4;
            float4 bv = *(const float4*)(Ws + nb * 16 + 4 * q);
#pragma unroll
            for (int f = 0; f < 2; f++) {
                mma_tf32(acc[f][t],
                         __float_as_uint(a0[f].x), __float_as_uint(a1[f].x),
                         __float_as_uint(a0[f].y), __float_as_uint(a1[f].y),
                         __float_as_uint(bv.x), __float_as_uint(bv.y));
                mma_tf32(acc[f][t],
                         __float_as_uint(a0[f].z), __float_as_uint(a1[f].z),
                         __float_as_uint(a0[f].w), __float_as_uint(a1[f].w),
                         __float_as_uint(bv.z), __float_as_uint(bv.w));
            }
        }

        if (c + 3 < NC) stage(c + 3);
        CP_COMMIT();                // unconditional: keeps wait_group accounting exact at tail
    }
    __syncthreads();   // all MMA/X reads done before epilogue overwrites Ys

    // ---- epilogue: +bias, celu, (round), permuted store to Ys ----
#pragma unroll
    for (int f = 0; f < 2; f++) {
#pragma unroll
        for (int t = 0; t < NT; t++) {
            const int r = m_idx * 32 + f * 16 + g4;
            const int cn = n_idx * (N / 4) + t * 8 + 2 * q;
            const float bv0 = __ldg(bg + cn), bv1 = __ldg(bg + cn + 1);
            float v0 = celu_f(acc[f][t][0] + bv0);
            float v1 = celu_f(acc[f][t][1] + bv1);
            float v2 = celu_f(acc[f][t][2] + bv0);
            float v3 = celu_f(acc[f][t][3] + bv1);
            if (ROUND) {
                v0 = tf32rf(v0); v1 = tf32rf(v1);
                v2 = tf32rf(v2); v3 = tf32rf(v3);
            }
            const int w0 = cn & 15, w1 = (cn + 1) & 15;
            const int p0 = (cn & ~15) + (((w0 & 3) << 2) | (w0 >> 2));
            const int p1 = (cn & ~15) + (((w1 & 3) << 2) | (w1 >> 2));
            Ys[r * LDY + p0] = v0;
            Ys[r * LDY + p1] = v1;
            Ys[(r + 8) * LDY + p0] = v2;
            Ys[(r + 8) * LDY + p1] = v3;
        }
    }
    __syncthreads();
}

// ---------------- fused kernel ----------------
__global__ void __launch_bounds__(512, 1)
aev_mlp_mma(const float* __restrict__ fullaev, const int* __restrict__ species,
            const float* __restrict__ b0, const float* __restrict__ b1,
            const float* __restrict__ b2,
            const float* __restrict__ W3, const float* __restrict__ b3)
{
    extern __shared__ float sm[];
    float* Ys = sm;
    const float* WcF = sm + OFF_W;
    const float* XcF = sm;                  // X ring overlays Ys during L0
    const uint32_t smU = smem_u32(sm);
    const uint32_t wcU = smU + OFF_W * 4;
    const uint32_t xcU = smU;

    const int a = blockIdx.y;
    const int bbase = blockIdx.x * 128;
    const int tid = threadIdx.x;
    const int lane = tid & 31, wid = tid >> 5;
    const int m_idx = wid >> 2, n_idx = wid & 3;
    const int s = species[a];
    const float* xg = fullaev + (size_t)bbase * 98304 + (size_t)a * 384;

    layer_run<384, 256, true,  true >(g_Wp0 + (size_t)s * (24 * 256 * 16), b0 + s * 256, xg,
                                      Ys, WcF, XcF, wcU, xcU, tid, lane, m_idx, n_idx);
    layer_run<256, 192, false, true >(g_Wp1 + (size_t)s * (16 * 192 * 16), b1 + s * 192, xg,
                                      Ys, WcF, XcF, wcU, xcU, tid, lane, m_idx, n_idx);
    layer_run<192, 160, false, false>(g_Wp2 + (size_t)s * (12 * 160 * 16), b2 + s * 160, xg,
                                      Ys, WcF, XcF, wcU, xcU, tid, lane, m_idx, n_idx);

    // ---- layer 3: dot(Y2[r, 0:160], w3) + b3, celu ----
    if (tid < 128) {
        const float* w = W3 + s * 160;
        float s0 = 0.f, s1 = 0.f, s2 = 0.f, s3 = 0.f;
        const float* yr = Ys + tid * LDY;
#pragma unroll
        for (int k = 0; k < 160; k += 4) {
            const int gb = k & ~15;
            const int w0 = k & 15;
            const int pA = gb + (((w0 & 3) << 2) | (w0 >> 2));
            const int w1 = (k + 1) & 15, w2 = (k + 2) & 15, w3i = (k + 3) & 15;
            const int pB = gb + (((w1 & 3) << 2) | (w1 >> 2));
            const int pC = gb + (((w2 & 3) << 2) | (w2 >> 2));
            const int pD = gb + (((w3i & 3) << 2) | (w3i >> 2));
            s0 = fmaf(yr[pA], __ldg(w + k + 0), s0);
            s1 = fmaf(yr[pB], __ldg(w + k + 1), s1);
            s2 = fmaf(yr[pC], __ldg(w + k + 2), s2);
            s3 = fmaf(yr[pD], __ldg(w + k + 3), s3);
        }
        float acc = ((s0 + s1) + (s2 + s3)) + __ldg(b3 + s);
        g_partial[(size_t)a * 1024 + bbase + tid] = celu_f(acc);
    }
}

// ---------------- deterministic two-stage reduction ----------------
__global__ void reduce1() {
    int b = blockIdx.x * 256 + threadIdx.x;
    int ag = blockIdx.y;
    float acc = 0.f;
#pragma unroll
    for (int i = 0; i < 32; i++) acc += g_partial[(size_t)(ag * 32 + i) * 1024 + b];
    g_red[ag * 1024 + b] = acc;
}
__global__ void reduce2(float* __restrict__ out) {
    int b = blockIdx.x * 256 + threadIdx.x;
    float acc = 0.f;
#pragma unroll
    for (int g = 0; g < 8; g++) acc += g_red[g * 1024 + b];
    out[b] = acc;
}

extern "C" void kernel_launch(void* const* d_in, const int* in_sizes, int n_in,
                              void* d_out, int out_size) {
    const float* fullaev = (const float*)d_in[0];
    const int*   species = (const int*)d_in[1];
    const float* W0 = (const float*)d_in[2];
    const float* b0 = (const float*)d_in[3];
    const float* W1 = (const float*)d_in[4];
    const float* b1 = (const float*)d_in[5];
    const float* W2 = (const float*)d_in[6];
    const float* b2 = (const float*)d_in[7];
    const float* W3 = (const float*)d_in[8];
    const float* b3 = (const float*)d_in[9];

    prep_w<384, 256, 0><<<(4 * 384 * 256 + 255) / 256, 256>>>(W0);
    prep_w<256, 192, 1><<<(4 * 256 * 192 + 255) / 256, 256>>>(W1);
    prep_w<192, 160, 2><<<(4 * 192 * 160 + 255) / 256, 256>>>(W2);

    cudaFuncSetAttribute(aev_mlp_mma, cudaFuncAttributeMaxDynamicSharedMemorySize, SMEM_BYTES);
    dim3 grid(8, 256);   // (B-tiles of 128, atoms)
    aev_mlp_mma<<<grid, 512, SMEM_BYTES>>>(fullaev, species, b0, b1, b2, W3, b3);

    reduce1<<<dim3(4, 8), 256>>>();
    reduce2<<<4, 256>>>((float*)d_out);
}

// round 10
// speedup vs baseline: 1.6122x; 1.0536x over previous
#include <cuda_runtime.h>
#include <cstdint>
#include <math.h>

#define ALPHA_CELU 0.1f

// ---------------- device scratch ----------------
__device__ float g_Wp0[4 * 24 * 256 * 16];   // [s][chunk][n][16 perm k]
__device__ float g_Wp1[4 * 16 * 192 * 16];
__device__ float g_Wp2[4 * 12 * 160 * 16];
__device__ float g_partial[256 * 1024];      // [atom][b]
__device__ float g_red[8 * 1024];

// ---------------- helpers ----------------
// Branchless CELU: max(x,0) + min(0, alpha*(exp(x/alpha)-1)).
__device__ __forceinline__ float celu_f(float x) {
    float e = __expf(x * (1.f / ALPHA_CELU));
    return fmaxf(x, 0.f) + fminf(0.f, ALPHA_CELU * (e - 1.f));
}
__device__ __forceinline__ uint32_t tf32r(float x) {   // RNA round to tf32
    uint32_t u;
    asm("cvt.rna.tf32.f32 %0, %1;" : "=r"(u) : "f"(x));
    return u;
}
__device__ __forceinline__ float tf32rf(float x) { return __uint_as_float(tf32r(x)); }
__device__ __forceinline__ uint32_t smem_u32(const void* p) {
    uint32_t a;
    asm("{ .reg .u64 t; cvta.to.shared.u64 t, %1; cvt.u32.u64 %0, t; }" : "=r"(a) : "l"(p));
    return a;
}
__device__ __forceinline__ void mma_tf32(float c[4],
                                         uint32_t a0, uint32_t a1, uint32_t a2, uint32_t a3,
                                         uint32_t b0, uint32_t b1) {
    asm volatile("mma.sync.aligned.m16n8k8.row.col.f32.tf32.tf32.f32 "
                 "{%0,%1,%2,%3}, {%4,%5,%6,%7}, {%8,%9}, {%0,%1,%2,%3};"
                 : "+f"(c[0]), "+f"(c[1]), "+f"(c[2]), "+f"(c[3])
                 : "r"(a0), "r"(a1), "r"(a2), "r"(a3), "r"(b0), "r"(b1));
}
#define CP_ASYNC16(dst, src) \
    asm volatile("cp.async.ca.shared.global [%0], [%1], 16;" :: "r"(dst), "l"(src))
#define CP_COMMIT() asm volatile("cp.async.commit_group;" ::: "memory")
#define CP_WAIT1()  asm volatile("cp.async.wait_group 1;" ::: "memory")
#define CP_WAIT2()  asm volatile("cp.async.wait_group 2;" ::: "memory")

// ---------------- smem layout (floats) ----------------
// Ys: 128 x 272.  X ring (L0 only, 4 slots x 2560 floats) OVERLAYS Ys.
// W ring: 4 slots x 4096 floats after Ys.
#define LDY 272
#define OFF_W (128 * LDY)                 // 34816 floats
#define SMEM_FLOATS (OFF_W + 4 * 4096)    // 51200 floats
#define SMEM_BYTES (SMEM_FLOATS * 4)      // 204800 B

// ---------------- weight prep: [S,K,N] -> [s][k/16][n][perm(k&15)] tf32 ----------------
template<int K, int N, int WHICH>
__global__ void prep_w(const float* __restrict__ W) {
    int i = blockIdx.x * blockDim.x + threadIdx.x;
    if (i >= 4 * K * N) return;
    float* dst = (WHICH == 0) ? g_Wp0 : (WHICH == 1) ? g_Wp1 : g_Wp2;
    int n = i % N, k = (i / N) % K, s = i / (N * K);
    int chunk = k >> 4, w = k & 15;
    int p = ((w & 3) << 2) | (w >> 2);
    dst[((size_t)(s * (K / 16) + chunk) * N + n) * 16 + p] = __uint_as_float(tf32r(W[i]));
}

// ---------------- one layer (512 threads, warp grid 4m x 4n, warp tile 32 x N/4) ----------------
template<int K, int N, bool IS_L0, bool ROUND>
__device__ __forceinline__ void layer_run(
    const float* __restrict__ Wp, const float* __restrict__ bg,
    const float* __restrict__ xg,
    float* __restrict__ Ys, const float* __restrict__ WcF, const float* __restrict__ XcF,
    uint32_t wcU, uint32_t xcU,
    int tid, int lane, int m_idx, int n_idx)
{
    constexpr int NT = N / 32;                // n8 tiles per warp (8 / 6 / 5)
    constexpr int NC = K / 16;
    constexpr int WI = (N * 4 + 511) / 512;   // W float4s per thread per chunk

    float acc[2][NT][4];
#pragma unroll
    for (int f = 0; f < 2; f++)
#pragma unroll
        for (int t = 0; t < NT; t++)
#pragma unroll
            for (int j = 0; j < 4; j++) acc[f][t][j] = 0.f;

    const int xrow = tid >> 2, xblk = tid & 3;   // 512 thr = 512 float4 = 128 rows x 4

    auto stage = [&](int c) {
        const char* wsrc = (const char*)(Wp + (size_t)c * N * 16);
        const uint32_t wdst = wcU + (uint32_t)(c & 3) * 16384u;
#pragma unroll
        for (int j = 0; j < WI; j++) {
            int i = tid + j * 512;
            if ((N * 4) % 512 == 0 || i < N * 4)
                CP_ASYNC16(wdst + (uint32_t)i * 16u, wsrc + (size_t)i * 16);
        }
        if (IS_L0) {
            const uint32_t xdst = xcU + (uint32_t)(c & 3) * 10240u;
            const float* src = xg + (size_t)xrow * 98304 + c * 16 + xblk * 4;
            CP_ASYNC16(xdst + (uint32_t)(xrow * 80 + xblk * 16), src);
        }
    };

    const int q = lane & 3, g4 = lane >> 2;

    // A-fragment loader for chunk c (into caller registers)
    auto load_frags = [&](int c, float4 a0[2], float4 a1[2]) {
        if (IS_L0) {
            const float* Xs = XcF + (c & 3) * 2560;
#pragma unroll
            for (int f = 0; f < 2; f++) {
                const float* p0 = Xs + (m_idx * 32 + f * 16 + g4) * 20 + q;
                const float* p1 = p0 + 8 * 20;
                a0[f].x = tf32rf(p0[0]);  a0[f].y = tf32rf(p0[4]);
                a0[f].z = tf32rf(p0[8]);  a0[f].w = tf32rf(p0[12]);
                a1[f].x = tf32rf(p1[0]);  a1[f].y = tf32rf(p1[4]);
                a1[f].z = tf32rf(p1[8]);  a1[f].w = tf32rf(p1[12]);
            }
        } else {
            const int colb = c * 16 + 4 * q;
#pragma unroll
            for (int f = 0; f < 2; f++) {
                const float* p0 = Ys + (m_idx * 32 + f * 16 + g4) * LDY + colb;
                a0[f] = *(const float4*)p0;
                a1[f] = *(const float4*)(p0 + 8 * LDY);
            }
        }
    };

    // depth-3 pipeline prologue
    stage(0); CP_COMMIT();
    stage(1); CP_COMMIT();
    stage(2); CP_COMMIT();

    float4 a0[2], a1[2];
    CP_WAIT2();                 // group 0 landed
    __syncthreads();            // publish chunk 0
    load_frags(0, a0, a1);

#pragma unroll 4
    for (int c = 0; c < NC; c++) {
        // ---- prefetch chunk c+1's A fragments (overlaps chunk c's MMAs) ----
        float4 na0[2], na1[2];
        if (c + 1 < NC) {
            CP_WAIT1();         // groups 0..c+1 landed (c+2 may be pending)
            __syncthreads();    // publish chunk c+1; readers of old slots done
            load_frags(c + 1, na0, na1);
        }

        // ---- MMA over N tiles for chunk c (uses a0/a1, independent of prefetch) ----
        const float* Ws = WcF + (c & 3) * 4096;
#pragma unroll
        for (int t = 0; t < NT; t++) {
            const int nb = n_idx * (N / 4) + t * 8 + g4;
            float4 bv = *(const float4*)(Ws + nb * 16 + 4 * q);
#pragma unroll
            for (int f = 0; f < 2; f++) {
                mma_tf32(acc[f][t],
                         __float_as_uint(a0[f].x), __float_as_uint(a1[f].x),
                         __float_as_uint(a0[f].y), __float_as_uint(a1[f].y),
                         __float_as_uint(bv.x), __float_as_uint(bv.y));
                mma_tf32(acc[f][t],
                         __float_as_uint(a0[f].z), __float_as_uint(a1[f].z),
                         __float_as_uint(a0[f].w), __float_as_uint(a1[f].w),
                         __float_as_uint(bv.z), __float_as_uint(bv.w));
            }
        }

        if (c + 3 < NC) stage(c + 3);
        CP_COMMIT();            // unconditional: keeps wait_group accounting exact

        if (c + 1 < NC) {
            a0[0] = na0[0]; a0[1] = na0[1];
            a1[0] = na1[0]; a1[1] = na1[1];
        }
    }
    __syncthreads();   // all MMA/B/X reads done before epilogue overwrites Ys

    // ---- epilogue: +bias, celu, (round), permuted store to Ys ----
#pragma unroll
    for (int f = 0; f < 2; f++) {
#pragma unroll
        for (int t = 0; t < NT; t++) {
            const int r = m_idx * 32 + f * 16 + g4;
            const int cn = n_idx * (N / 4) + t * 8 + 2 * q;
            const float bv0 = __ldg(bg + cn), bv1 = __ldg(bg + cn + 1);
            float v0 = celu_f(acc[f][t][0] + bv0);
            float v1 = celu_f(acc[f][t][1] + bv1);
            float v2 = celu_f(acc[f][t][2] + bv0);
            float v3 = celu_f(acc[f][t][3] + bv1);
            if (ROUND) {
                v0 = tf32rf(v0); v1 = tf32rf(v1);
                v2 = tf32rf(v2); v3 = tf32rf(v3);
            }
            const int w0 = cn & 15, w1 = (cn + 1) & 15;
            const int p0 = (cn & ~15) + (((w0 & 3) << 2) | (w0 >> 2));
            const int p1 = (cn & ~15) + (((w1 & 3) << 2) | (w1 >> 2));
            Ys[r * LDY + p0] = v0;
            Ys[r * LDY + p1] = v1;
            Ys[(r + 8) * LDY + p0] = v2;
            Ys[(r + 8) * LDY + p1] = v3;
        }
    }
    __syncthreads();
}

// ---------------- fused kernel ----------------
__global__ void __launch_bounds__(512, 1)
aev_mlp_mma(const float* __restrict__ fullaev, const int* __restrict__ species,
            const float* __restrict__ b0, const float* __restrict__ b1,
            const float* __restrict__ b2,
            const float* __restrict__ W3, const float* __restrict__ b3)
{
    extern __shared__ float sm[];
    float* Ys = sm;
    const float* WcF = sm + OFF_W;
    const float* XcF = sm;                  // X ring overlays Ys during L0
    const uint32_t smU = smem_u32(sm);
    const uint32_t wcU = smU + OFF_W * 4;
    const uint32_t xcU = smU;

    const int a = blockIdx.y;
    const int bbase = blockIdx.x * 128;
    const int tid = threadIdx.x;
    const int lane = tid & 31, wid = tid >> 5;
    const int m_idx = wid >> 2, n_idx = wid & 3;
    const int s = species[a];
    const float* xg = fullaev + (size_t)bbase * 98304 + (size_t)a * 384;

    layer_run<384, 256, true,  true >(g_Wp0 + (size_t)s * (24 * 256 * 16), b0 + s * 256, xg,
                                      Ys, WcF, XcF, wcU, xcU, tid, lane, m_idx, n_idx);
    layer_run<256, 192, false, true >(g_Wp1 + (size_t)s * (16 * 192 * 16), b1 + s * 192, xg,
                                      Ys, WcF, XcF, wcU, xcU, tid, lane, m_idx, n_idx);
    layer_run<192, 160, false, false>(g_Wp2 + (size_t)s * (12 * 160 * 16), b2 + s * 160, xg,
                                      Ys, WcF, XcF, wcU, xcU, tid, lane, m_idx, n_idx);

    // ---- layer 3: dot(Y2[r, 0:160], w3) + b3, celu ----
    if (tid < 128) {
        const float* w = W3 + s * 160;
        float s0 = 0.f, s1 = 0.f, s2 = 0.f, s3 = 0.f;
        const float* yr = Ys + tid * LDY;
#pragma unroll
        for (int k = 0; k < 160; k += 4) {
            const int gb = k & ~15;
            const int w0 = k & 15;
            const int pA = gb + (((w0 & 3) << 2) | (w0 >> 2));
            const int w1 = (k + 1) & 15, w2 = (k + 2) & 15, w3i = (k + 3) & 15;
            const int pB = gb + (((w1 & 3) << 2) | (w1 >> 2));
            const int pC = gb + (((w2 & 3) << 2) | (w2 >> 2));
            const int pD = gb + (((w3i & 3) << 2) | (w3i >> 2));
            s0 = fmaf(yr[pA], __ldg(w + k + 0), s0);
            s1 = fmaf(yr[pB], __ldg(w + k + 1), s1);
            s2 = fmaf(yr[pC], __ldg(w + k + 2), s2);
            s3 = fmaf(yr[pD], __ldg(w + k + 3), s3);
        }
        float acc = ((s0 + s1) + (s2 + s3)) + __ldg(b3 + s);
        g_partial[(size_t)a * 1024 + bbase + tid] = celu_f(acc);
    }
}

// ---------------- deterministic two-stage reduction ----------------
__global__ void reduce1() {
    int b = blockIdx.x * 256 + threadIdx.x;
    int ag = blockIdx.y;
    float acc = 0.f;
#pragma unroll
    for (int i = 0; i < 32; i++) acc += g_partial[(size_t)(ag * 32 + i) * 1024 + b];
    g_red[ag * 1024 + b] = acc;
}
__global__ void reduce2(float* __restrict__ out) {
    int b = blockIdx.x * 256 + threadIdx.x;
    float acc = 0.f;
#pragma unroll
    for (int g = 0; g < 8; g++) acc += g_red[g * 1024 + b];
    out[b] = acc;
}

extern "C" void kernel_launch(void* const* d_in, const int* in_sizes, int n_in,
                              void* d_out, int out_size) {
    const float* fullaev = (const float*)d_in[0];
    const int*   species = (const int*)d_in[1];
    const float* W0 = (const float*)d_in[2];
    const float* b0 = (const float*)d_in[3];
    const float* W1 = (const float*)d_in[4];
    const float* b1 = (const float*)d_in[5];
    const float* W2 = (const float*)d_in[6];
    const float* b2 = (const float*)d_in[7];
    const float* W3 = (const float*)d_in[8];
    const float* b3 = (const float*)d_in[9];

    prep_w<384, 256, 0><<<(4 * 384 * 256 + 255) / 256, 256>>>(W0);
    prep_w<256, 192, 1><<<(4 * 256 * 192 + 255) / 256, 256>>>(W1);
    prep_w<192, 160, 2><<<(4 * 192 * 160 + 255) / 256, 256>>>(W2);

    cudaFuncSetAttribute(aev_mlp_mma, cudaFuncAttributeMaxDynamicSharedMemorySize, SMEM_BYTES);
    dim3 grid(8, 256);   // (B-tiles of 128, atoms)
    aev_mlp_mma<<<grid, 512, SMEM_BYTES>>>(fullaev, species, b0, b1, b2, W3, b3);

    reduce1<<<dim3(4, 8), 256>>>();
    reduce2<<<4, 256>>>((float*)d_out);
}